// round 6
// baseline (speedup 1.0000x reference)
#include <cuda_runtime.h>
#include <math.h>

#define B_   8
#define T_   512
#define FIN_ 256
#define D_   128
#define C_   16          // chunks per batch
#define L_   32          // chunk length (T_/C_)
#define JH_  64          // j-half width

typedef unsigned long long u64;

// ---------------- f32x2 packed helpers ----------------
__device__ __forceinline__ void fma2(u64& acc, u64 a, u64 b) {
    asm("fma.rn.f32x2 %0, %1, %2, %3;" : "=l"(acc) : "l"(a), "l"(b), "l"(acc));
}
__device__ __forceinline__ u64 bc2(float a) {
    u64 r; asm("mov.b64 %0, {%1, %1};" : "=l"(r) : "f"(a)); return r;
}
__device__ __forceinline__ float2 unp2(u64 v) {
    float2 r; asm("mov.b64 {%0, %1}, %2;" : "=f"(r.x), "=f"(r.y) : "l"(v)); return r;
}

// ---------------- scratch ----------------
__device__ __align__(16) float g_K[B_*T_*D_];
__device__ __align__(16) float g_Q[B_*T_*D_];
__device__ __align__(16) float g_V[B_*T_*D_];
__device__ __align__(16) float g_R[B_*T_*D_];      // xn @ Ws + bs
__device__ __align__(16) float g_num[B_*T_*D_];
__device__ __align__(16) float g_den[B_*T_];
__device__ __align__(16) float g_Soff[B_*C_*D_*D_];// chunk sums -> exclusive prefix
__device__ __align__(16) float g_Zsum[B_*C_*D_];   // chunk K sums -> exclusive prefix

// ---------------- k1: fused LayerNorm + projection (m = blockIdx.y) ----------------
__global__ void k1_ln_proj(const float* __restrict__ x,
                           const float* __restrict__ gamma, const float* __restrict__ beta,
                           const float* __restrict__ Wk, const float* __restrict__ Wq,
                           const float* __restrict__ Wv, const float* __restrict__ Ws,
                           const float* __restrict__ bs) {
    extern __shared__ float sm[];
    float* xb = sm;               // 32*256
    float* wb = sm + 32*FIN_;     // 32*128
    const int tid = threadIdx.x;       // 128
    const int w   = tid >> 5, lane = tid & 31;
    const int tr  = tid >> 4;          // 0..7
    const int tc  = tid & 15;          // 0..15
    const int row0 = blockIdx.x * 32;
    const int m    = blockIdx.y;       // 0:K 1:Q 2:V 3:R

    const float* Wp = (m==0) ? Wk : (m==1) ? Wq : (m==2) ? Wv : Ws;
    float*       Op = (m==0) ? g_K : (m==1) ? g_Q : (m==2) ? g_V : g_R;

    {
        const float4* xg = (const float4*)(x + (size_t)row0 * FIN_);
        for (int q = tid; q < 32*FIN_/4; q += 128) ((float4*)xb)[q] = xg[q];
    }
    float gv[8], bv[8];
#pragma unroll
    for (int k = 0; k < 8; k++) { gv[k] = gamma[lane + 32*k]; bv[k] = beta[lane + 32*k]; }
    __syncthreads();

#pragma unroll
    for (int rr = 0; rr < 8; rr++) {
        const int r = w*8 + rr;
        float s = 0.f, ss = 0.f, xv[8];
#pragma unroll
        for (int k = 0; k < 8; k++) { float v = xb[r*FIN_ + lane + 32*k]; xv[k] = v; s += v; ss += v*v; }
#pragma unroll
        for (int off = 16; off; off >>= 1) {
            s  += __shfl_xor_sync(0xffffffffu, s,  off);
            ss += __shfl_xor_sync(0xffffffffu, ss, off);
        }
        const float mu   = s * (1.0f/FIN_);
        const float rstd = rsqrtf(ss*(1.0f/FIN_) - mu*mu + 1e-5f);
#pragma unroll
        for (int k = 0; k < 8; k++)
            xb[r*FIN_ + lane + 32*k] = (xv[k]-mu)*rstd*gv[k] + bv[k];
    }
    __syncthreads();

    u64 acc2[4][4];
#pragma unroll
    for (int u = 0; u < 4; u++)
#pragma unroll
        for (int p = 0; p < 4; p++) acc2[u][p] = 0ull;

    for (int kc = 0; kc < FIN_; kc += 32) {
        __syncthreads();
        for (int q = tid; q < 32*D_/4; q += 128)
            ((float4*)wb)[q] = ((const float4*)(Wp + (size_t)kc*D_))[q];
        __syncthreads();
#pragma unroll
        for (int k = 0; k < 32; k++) {
            const ulonglong2 wA = ((const ulonglong2*)(wb + k*D_))[tc*2];
            const ulonglong2 wB = ((const ulonglong2*)(wb + k*D_))[tc*2+1];
#pragma unroll
            for (int u = 0; u < 4; u++) {
                const u64 aa = bc2(xb[(tr*4+u)*FIN_ + kc + k]);
                fma2(acc2[u][0], aa, wA.x);
                fma2(acc2[u][1], aa, wA.y);
                fma2(acc2[u][2], aa, wB.x);
                fma2(acc2[u][3], aa, wB.y);
            }
        }
    }

    float badd[8] = {0,0,0,0,0,0,0,0};
    if (m == 3) {
        float4 t0 = ((const float4*)bs)[tc*2];
        float4 t1 = ((const float4*)bs)[tc*2+1];
        badd[0]=t0.x; badd[1]=t0.y; badd[2]=t0.z; badd[3]=t0.w;
        badd[4]=t1.x; badd[5]=t1.y; badd[6]=t1.z; badd[7]=t1.w;
    }
#pragma unroll
    for (int u = 0; u < 4; u++) {
        float o[8];
#pragma unroll
        for (int p = 0; p < 4; p++) {
            const float2 t = unp2(acc2[u][p]);
            o[2*p] = t.x; o[2*p+1] = t.y;
        }
#pragma unroll
        for (int v = 0; v < 8; v++) {
            float val = o[v];
            if (m <= 1) val = (val > 0.f) ? (val + 1.f) : expf(val);   // elu + 1
            o[v] = val + badd[v];
        }
        float* dst = Op + ((size_t)(row0 + tr*4 + u))*D_ + tc*8;
        *(float4*)(dst)   = make_float4(o[0], o[1], o[2], o[3]);
        *(float4*)(dst+4) = make_float4(o[4], o[5], o[6], o[7]);
    }
}

// ---------------- k2: per-chunk outer-product sums + per-chunk K sums ----------------
__global__ void k2_chunksum() {
    const int c = blockIdx.x, b = blockIdx.y;
    const int tid = threadIdx.x;   // 256
    __shared__ __align__(16) float Ks[L_][D_];
    __shared__ __align__(16) float Vs[L_][D_];
    {
        const float4* kg = (const float4*)(g_K + ((size_t)b*T_ + c*L_)*D_);
        const float4* vg = (const float4*)(g_V + ((size_t)b*T_ + c*L_)*D_);
        for (int q = tid; q < L_*D_/4; q += 256) { ((float4*)Ks)[q] = kg[q]; ((float4*)Vs)[q] = vg[q]; }
    }
    __syncthreads();

    if (tid < D_) {
        float zs = 0.f;
#pragma unroll
        for (int t = 0; t < L_; t++) zs += Ks[t][tid];
        g_Zsum[((size_t)(b*C_ + c))*D_ + tid] = zs;
    }

    const int tr = tid >> 4, tc = tid & 15;  // 16x16, micro 8x8
    const int i0 = tr*8, j0 = tc*8;
    float acc[8][8];
#pragma unroll
    for (int u = 0; u < 8; u++)
#pragma unroll
        for (int v = 0; v < 8; v++) acc[u][v] = 0.f;

    for (int t = 0; t < L_; t++) {
        float k8[8], v8[8];
        *(float4*)(k8)   = *(const float4*)&Ks[t][i0];
        *(float4*)(k8+4) = *(const float4*)&Ks[t][i0+4];
        *(float4*)(v8)   = *(const float4*)&Vs[t][j0];
        *(float4*)(v8+4) = *(const float4*)&Vs[t][j0+4];
#pragma unroll
        for (int u = 0; u < 8; u++)
#pragma unroll
            for (int v = 0; v < 8; v++) acc[u][v] += k8[u]*v8[v];
    }
    float* op = g_Soff + (((size_t)(b*C_ + c))*D_ + i0)*D_ + j0;
#pragma unroll
    for (int u = 0; u < 8; u++) {
        *(float4*)(op + (size_t)u*D_)     = make_float4(acc[u][0],acc[u][1],acc[u][2],acc[u][3]);
        *(float4*)(op + (size_t)u*D_ + 4) = make_float4(acc[u][4],acc[u][5],acc[u][6],acc[u][7]);
    }
}

// ---------------- k3: exclusive scan over c, float4-wide ----------------
__global__ void k3_scan() {
    const int gid = blockIdx.x * blockDim.x + threadIdx.x;
    if (gid < B_*D_*D_/4) {
        const int b = gid >> 12;
        const int q = gid & 4095;
        float4* p = ((float4*)g_Soff) + (size_t)b*C_*4096 + q;
        float4 v[C_];
#pragma unroll
        for (int c = 0; c < C_; c++) v[c] = p[(size_t)c*4096];
        float rx=0.f, ry=0.f, rz=0.f, rw=0.f;
#pragma unroll
        for (int c = 0; c < C_; c++) {
            const float4 t = v[c];
            v[c] = make_float4(rx, ry, rz, rw);
            rx += t.x; ry += t.y; rz += t.z; rw += t.w;
        }
#pragma unroll
        for (int c = 0; c < C_; c++) p[(size_t)c*4096] = v[c];
    } else if (gid < B_*D_*D_/4 + B_*D_/4) {
        const int zid = gid - B_*D_*D_/4;
        const int b = zid >> 5, q = zid & 31;
        float4* p = ((float4*)g_Zsum) + (size_t)b*C_*32 + q;
        float4 v[C_];
#pragma unroll
        for (int c = 0; c < C_; c++) v[c] = p[(size_t)c*32];
        float rx=0.f, ry=0.f, rz=0.f, rw=0.f;
#pragma unroll
        for (int c = 0; c < C_; c++) {
            const float4 t = v[c];
            v[c] = make_float4(rx, ry, rz, rw);
            rx += t.x; ry += t.y; rz += t.z; rw += t.w;
        }
#pragma unroll
        for (int c = 0; c < C_; c++) p[(size_t)c*32] = v[c];
    }
}

// ---------------- k4: j-split streaming scan + num/den. grid (C_, B_, 2) x 512 ----------------
__global__ void __launch_bounds__(512, 2)
k4_scan(const float* __restrict__ S0, const float* __restrict__ Z0,
        float* __restrict__ outS, float* __restrict__ outZ) {
    const int c = blockIdx.x, b = blockIdx.y, jh = blockIdx.z;
    const int tid = threadIdx.x;         // 512
    const int ig = tid >> 4;             // 0..31
    const int jg = tid & 15;             // 0..15
    const int i0 = ig << 2;              // 0..124
    const int j0 = jg << 2;              // 0..60 within half
    const int jbase = jh * JH_;          // global j offset of this half

    __shared__ __align__(16) float Ks[L_*D_];    // 4096
    __shared__ __align__(16) float Qs[L_*D_];    // 4096
    __shared__ __align__(16) float Vh[L_*JH_];   // 2048 (reused as Ssum stage later)
    __shared__ __align__(16) float A[L_*L_];     // 1024
    __shared__ float zv[D_];
    __shared__ float sden[L_];

    const size_t base = ((size_t)b*T_ + c*L_)*D_;

    // loads: K,Q full (2 float4/thread), V half (1 float4/thread)
    {
        ((float4*)Ks)[tid]       = ((const float4*)(g_K + base))[tid];
        ((float4*)Ks)[tid + 512] = ((const float4*)(g_K + base))[tid + 512];
        ((float4*)Qs)[tid]       = ((const float4*)(g_Q + base))[tid];
        ((float4*)Qs)[tid + 512] = ((const float4*)(g_Q + base))[tid + 512];
        const int t = tid >> 4;          // 0..31
        const int q = tid & 15;          // 0..15 float4 within half row
        ((float4*)Vh)[tid] = *(const float4*)(g_V + base + (size_t)t*D_ + jbase + q*4);
    }

    // state init
    float s[4][4];
    {
        const float* soff = g_Soff + ((size_t)(b*C_ + c)*D_ + i0)*D_ + jbase + j0;
        const float* s0g  = S0 + ((size_t)b*D_ + i0)*D_ + jbase + j0;
#pragma unroll
        for (int u = 0; u < 4; u++) {
            const float4 a = *(const float4*)(soff + (size_t)u*D_);
            const float4 z = *(const float4*)(s0g  + (size_t)u*D_);
            s[u][0] = a.x + z.x; s[u][1] = a.y + z.y;
            s[u][2] = a.z + z.z; s[u][3] = a.w + z.w;
        }
    }
    float zrun = 0.f;
    if (tid < D_) {
        zrun = Z0[b*D_ + tid] + g_Zsum[(size_t)(b*C_ + c)*D_ + tid];
        if (jh == 0) zv[tid] = zrun;
    }
    __syncthreads();

    // ---- phase 1: streaming scan, no syncs ----
    {
        float* op = outS + ((size_t)(b*T_ + c*L_))*D_*D_ + (size_t)i0*D_ + jbase + j0;
        float* zp = outZ + base;
        for (int tt = 0; tt < L_; tt++) {
            const float4 kv = *(const float4*)&Ks[tt*D_ + i0];
            const float4 vv = *(const float4*)&Vh[tt*JH_ + j0];
            const float kk[4] = {kv.x, kv.y, kv.z, kv.w};
#pragma unroll
            for (int u = 0; u < 4; u++) {
                s[u][0] += kk[u]*vv.x;
                s[u][1] += kk[u]*vv.y;
                s[u][2] += kk[u]*vv.z;
                s[u][3] += kk[u]*vv.w;
                __stcs((float4*)(op + (size_t)u*D_),
                       make_float4(s[u][0], s[u][1], s[u][2], s[u][3]));
            }
            if (jh == 0 && tid < D_) { zrun += Ks[tt*D_ + tid]; zp[tid] = zrun; }
            op += (size_t)D_*D_;
            zp += D_;
        }
    }

    // ---- phase 2a: masked A = QK^T (both halves compute); den in jh==0 ----
    if (tid < 256) {
        const int ti = tid >> 3;
        const int g  = tid & 7;
        float a4[4] = {0.f, 0.f, 0.f, 0.f};
        for (int k = 0; k < D_; k += 4) {
            const float4 qv = *(const float4*)&Qs[ti*D_ + k];
#pragma unroll
            for (int j = 0; j < 4; j++) {
                const float4 kv = *(const float4*)&Ks[(g*4+j)*D_ + k];
                a4[j] += qv.x*kv.x + qv.y*kv.y + qv.z*kv.z + qv.w*kv.w;
            }
        }
        float rsum = 0.f;
#pragma unroll
        for (int j = 0; j < 4; j++) {
            const int tj = g*4 + j;
            const float mval = (tj <= ti) ? a4[j] : 0.f;
            A[ti*L_ + tj] = mval;
            rsum += mval;
        }
        if (jh == 0) {
            float zp = 0.f;
#pragma unroll
            for (int k = 0; k < 16; k += 4) {
                const float4 qv = *(const float4*)&Qs[ti*D_ + g*16 + k];
                const float4 zz = *(const float4*)&zv[g*16 + k];
                zp += qv.x*zz.x + qv.y*zz.y + qv.z*zz.z + qv.w*zz.w;
            }
            float tot = rsum + zp;
#pragma unroll
            for (int off = 4; off; off >>= 1) tot += __shfl_down_sync(0xffffffffu, tot, off);
            if (g == 0) sden[ti] = tot;
        }
    }
    __syncthreads();

    // ---- phase 2b: numerator half. thread = (row = tid>>4, 4 cols = (tid&15)*4) ----
    const int row = tid >> 4;
    const int cg  = (tid & 15) * 4;
    float nacc[4] = {0.f, 0.f, 0.f, 0.f};
    // intra: masked A @ Vhalf
    for (int tj = 0; tj <= row; tj++) {
        const float a = A[row*L_ + tj];
        const float4 vv = *(const float4*)&Vh[tj*JH_ + cg];
        nacc[0] += a*vv.x; nacc[1] += a*vv.y;
        nacc[2] += a*vv.z; nacc[3] += a*vv.w;
    }
    // inter: Q @ (S0+Soff) half, staged 32 rows x 64 cols into Vh
    {
        const float* s0p = S0 + (size_t)b*D_*D_ + jbase;
        const float* sop = g_Soff + (size_t)(b*C_ + c)*D_*D_ + jbase;
        for (int kb = 0; kb < D_; kb += 32) {
            __syncthreads();
            {
                const int r = tid >> 4;          // 0..31
                const int q = tid & 15;          // 0..15
                const float4 x0 = __ldg((const float4*)(s0p + (size_t)(kb + r)*D_) + q);
                const float4 x1 = __ldg((const float4*)(sop + (size_t)(kb + r)*D_) + q);
                ((float4*)Vh)[tid] = make_float4(x0.x+x1.x, x0.y+x1.y, x0.z+x1.z, x0.w+x1.w);
            }
            __syncthreads();
#pragma unroll 8
            for (int k = 0; k < 32; k++) {
                const float qq = Qs[row*D_ + kb + k];
                const float4 sv = *(const float4*)&Vh[k*JH_ + cg];
                nacc[0] += qq*sv.x; nacc[1] += qq*sv.y;
                nacc[2] += qq*sv.z; nacc[3] += qq*sv.w;
            }
        }
    }
    *(float4*)(g_num + base + (size_t)row*D_ + jbase + cg) =
        make_float4(nacc[0], nacc[1], nacc[2], nacc[3]);
    if (jh == 0 && tid < L_)
        g_den[(size_t)b*T_ + c*L_ + tid] = sden[tid];
}

// ---------------- k5: out = relu(relu((num/den)@W1+b1)@W2+b2) + R ----------------
__global__ void k5_ffn(const float* __restrict__ W1, const float* __restrict__ b1_,
                       const float* __restrict__ W2, const float* __restrict__ b2_,
                       float* __restrict__ outO) {
    __shared__ __align__(16) float aBuf[32*D_];
    __shared__ __align__(16) float wBuf[32*D_];
    const int tid  = threadIdx.x;  // 256
    const int w    = tid >> 5, lane = tid & 31;
    const int row0 = blockIdx.x * 32;

#pragma unroll
    for (int rr = 0; rr < 4; rr++) {
        const int r = w*4 + rr;
        const size_t row = (size_t)row0 + r;
        const float rden = 1.0f / (g_den[row] + 1e-5f);
#pragma unroll
        for (int k = 0; k < 4; k++) {
            const int f = lane + 32*k;
            aBuf[r*D_ + f] = g_num[row*D_ + f] * rden;
        }
    }
    const int rowg = w, colg = lane;
    float acc[4][4];

#pragma unroll
    for (int u = 0; u < 4; u++)
#pragma unroll
        for (int v = 0; v < 4; v++) acc[u][v] = 0.f;
    for (int kc = 0; kc < D_; kc += 32) {
        __syncthreads();
        for (int q = tid; q < 32*D_/4; q += 256)
            ((float4*)wBuf)[q] = ((const float4*)(W1 + (size_t)kc*D_))[q];
        __syncthreads();
#pragma unroll
        for (int k = 0; k < 32; k++) {
            const float4 wv = ((const float4*)(wBuf + k*D_))[colg];
#pragma unroll
            for (int u = 0; u < 4; u++) {
                const float a = aBuf[(rowg*4+u)*D_ + kc + k];
                acc[u][0] += a*wv.x; acc[u][1] += a*wv.y;
                acc[u][2] += a*wv.z; acc[u][3] += a*wv.w;
            }
        }
    }
    __syncthreads();
    {
        const float4 b1v = ((const float4*)b1_)[colg];
#pragma unroll
        for (int u = 0; u < 4; u++) {
            float4 h;
            h.x = fmaxf(acc[u][0] + b1v.x, 0.f);
            h.y = fmaxf(acc[u][1] + b1v.y, 0.f);
            h.z = fmaxf(acc[u][2] + b1v.z, 0.f);
            h.w = fmaxf(acc[u][3] + b1v.w, 0.f);
            *(float4*)&aBuf[(rowg*4+u)*D_ + colg*4] = h;
        }
    }
#pragma unroll
    for (int u = 0; u < 4; u++)
#pragma unroll
        for (int v = 0; v < 4; v++) acc[u][v] = 0.f;
    for (int kc = 0; kc < D_; kc += 32) {
        __syncthreads();
        for (int q = tid; q < 32*D_/4; q += 256)
            ((float4*)wBuf)[q] = ((const float4*)(W2 + (size_t)kc*D_))[q];
        __syncthreads();
#pragma unroll
        for (int k = 0; k < 32; k++) {
            const float4 wv = ((const float4*)(wBuf + k*D_))[colg];
#pragma unroll
            for (int u = 0; u < 4; u++) {
                const float a = aBuf[(rowg*4+u)*D_ + kc + k];
                acc[u][0] += a*wv.x; acc[u][1] += a*wv.y;
                acc[u][2] += a*wv.z; acc[u][3] += a*wv.w;
            }
        }
    }
    {
        const float4 b2v = ((const float4*)b2_)[colg];
#pragma unroll
        for (int u = 0; u < 4; u++) {
            const size_t row = (size_t)row0 + rowg*4 + u;
            const float4 rv = *(const float4*)(g_R + row*D_ + colg*4);
            float4 o;
            o.x = fmaxf(acc[u][0] + b2v.x, 0.f) + rv.x;
            o.y = fmaxf(acc[u][1] + b2v.y, 0.f) + rv.y;
            o.z = fmaxf(acc[u][2] + b2v.z, 0.f) + rv.z;
            o.w = fmaxf(acc[u][3] + b2v.w, 0.f) + rv.w;
            *(float4*)(outO + row*D_ + colg*4) = o;
        }
    }
}

// ---------------- launch ----------------
extern "C" void kernel_launch(void* const* d_in, const int* in_sizes, int n_in,
                              void* d_out, int out_size) {
    const float* x     = (const float*)d_in[0];
    const float* S0    = (const float*)d_in[1];
    const float* Z0    = (const float*)d_in[2];
    const float* gamma = (const float*)d_in[3];
    const float* beta  = (const float*)d_in[4];
    const float* Wk    = (const float*)d_in[5];
    const float* Wq    = (const float*)d_in[6];
    const float* Wv    = (const float*)d_in[7];
    const float* W1    = (const float*)d_in[8];
    const float* b1    = (const float*)d_in[9];
    const float* W2    = (const float*)d_in[10];
    const float* b2    = (const float*)d_in[11];
    const float* Ws    = (const float*)d_in[12];
    const float* bs    = (const float*)d_in[13];

    float* outO = (float*)d_out;                       // [B,T,D]
    float* outS = outO + (size_t)B_*T_*D_;             // [B,T,D*D]
    float* outZ = outS + (size_t)B_*T_*D_*D_;          // [B,T,D]

    const int smem_k1 = (32*FIN_ + 32*D_) * sizeof(float);   // 49152

    k1_ln_proj<<<dim3((B_*T_)/32, 4), 128, smem_k1>>>(x, gamma, beta, Wk, Wq, Wv, Ws, bs);
    k2_chunksum<<<dim3(C_, B_), 256>>>();
    k3_scan<<<(B_*D_*D_/4 + B_*D_/4 + 255)/256, 256>>>();
    k4_scan<<<dim3(C_, B_, 2), 512>>>(S0, Z0, outS, outZ);
    k5_ffn<<<(B_*T_)/32, 256>>>(W1, b1, W2, b2, outO);
}

// round 7
// speedup vs baseline: 1.0849x; 1.0849x over previous
#include <cuda_runtime.h>
#include <math.h>

#define B_   8
#define T_   512
#define FIN_ 256
#define D_   128
#define C_   16          // chunks per batch
#define L_   32          // chunk length
#define BH_  4           // batches per half-chain
#define JH_  64          // j-half width in k4

typedef unsigned long long u64;

__device__ __forceinline__ void fma2(u64& acc, u64 a, u64 b) {
    asm("fma.rn.f32x2 %0, %1, %2, %3;" : "=l"(acc) : "l"(a), "l"(b), "l"(acc));
}
__device__ __forceinline__ u64 bc2(float a) {
    u64 r; asm("mov.b64 %0, {%1, %1};" : "=l"(r) : "f"(a)); return r;
}
__device__ __forceinline__ float2 unp2(u64 v) {
    float2 r; asm("mov.b64 {%0, %1}, %2;" : "=f"(r.x), "=f"(r.y) : "l"(v)); return r;
}

// ---------------- scratch ----------------
__device__ __align__(16) float g_XN[B_*T_*FIN_];
__device__ __align__(16) float g_K[B_*T_*D_];
__device__ __align__(16) float g_Q[B_*T_*D_];
__device__ __align__(16) float g_V[B_*T_*D_];
__device__ __align__(16) float g_R[B_*T_*D_];
__device__ __align__(16) float g_num[B_*T_*D_];
__device__ __align__(16) float g_den[B_*T_];
__device__ __align__(16) float g_Soff[B_*C_*D_*D_];
__device__ __align__(16) float g_Zsum[B_*C_*D_];

// ---------------- k0: LayerNorm (per half) ----------------
__global__ void k0_ln(const float* __restrict__ x, const float* __restrict__ gamma,
                      const float* __restrict__ beta, int row_off) {
    const int tid  = threadIdx.x;         // 256
    const int w    = tid >> 5, lane = tid & 31;
    const int row0 = row_off + blockIdx.x * 32;

    float gv[8], bv[8];
#pragma unroll
    for (int k = 0; k < 8; k++) { gv[k] = gamma[lane + 32*k]; bv[k] = beta[lane + 32*k]; }

#pragma unroll
    for (int rr = 0; rr < 4; rr++) {
        const size_t r = (size_t)row0 + w*4 + rr;
        float s = 0.f, ss = 0.f, xv[8];
#pragma unroll
        for (int k = 0; k < 8; k++) {
            float v = x[r*FIN_ + lane + 32*k];
            xv[k] = v; s += v; ss += v*v;
        }
#pragma unroll
        for (int off = 16; off; off >>= 1) {
            s  += __shfl_xor_sync(0xffffffffu, s,  off);
            ss += __shfl_xor_sync(0xffffffffu, ss, off);
        }
        const float mu   = s * (1.0f/FIN_);
        const float rstd = rsqrtf(ss*(1.0f/FIN_) - mu*mu + 1e-5f);
#pragma unroll
        for (int k = 0; k < 8; k++)
            g_XN[r*FIN_ + lane + 32*k] = (xv[k]-mu)*rstd*gv[k] + bv[k];
    }
}

// ---------------- k1 v3: 128x128 tile GEMM, 8x8 micro, f32x2 ----------------
// grid (tiles, 4) x 256 threads. smem: xb[128][36] + wb[32][128]
#define XPITCH 36
__global__ void __launch_bounds__(256)
k1_proj(const float* __restrict__ Wk, const float* __restrict__ Wq,
        const float* __restrict__ Wv, const float* __restrict__ Ws,
        const float* __restrict__ bs, int row_off) {
    __shared__ __align__(16) float xb[128*XPITCH];
    __shared__ __align__(16) float wb[32*D_];
    const int tid = threadIdx.x;
    const int tr  = tid >> 4;           // 0..15
    const int tc  = tid & 15;           // 0..15
    const int row0 = row_off + blockIdx.x * 128;
    const int m    = blockIdx.y;        // 0:K 1:Q 2:V 3:R

    const float* Wp = (m==0) ? Wk : (m==1) ? Wq : (m==2) ? Wv : Ws;
    float*       Op = (m==0) ? g_K : (m==1) ? g_Q : (m==2) ? g_V : g_R;

    u64 acc2[8][4];
#pragma unroll
    for (int u = 0; u < 8; u++)
#pragma unroll
        for (int p = 0; p < 4; p++) acc2[u][p] = 0ull;

    for (int kc = 0; kc < FIN_; kc += 32) {
        __syncthreads();
        // stage x chunk: 128 rows x 32 k  (1024 float4)
#pragma unroll
        for (int p = 0; p < 4; p++) {
            const int idx = p*256 + tid;
            const int r = idx >> 3, cc = idx & 7;
            const float4 v = *(const float4*)(g_XN + ((size_t)row0 + r)*FIN_ + kc + cc*4);
            *(float4*)&xb[r*XPITCH + cc*4] = v;
        }
        // stage w chunk: 32 k x 128 cols (1024 float4)
#pragma unroll
        for (int p = 0; p < 4; p++) {
            const int idx = p*256 + tid;
            const int r = idx >> 5, cc = idx & 31;
            const float4 v = *(const float4*)(Wp + ((size_t)kc + r)*D_ + cc*4);
            *(float4*)&wb[r*D_ + cc*4] = v;
        }
        __syncthreads();

#pragma unroll
        for (int k = 0; k < 32; k += 2) {
            const ulonglong2 wa0 = *(const ulonglong2*)&wb[k*D_ + tc*8];
            const ulonglong2 wa1 = *(const ulonglong2*)&wb[k*D_ + tc*8 + 4];
            const ulonglong2 wb0 = *(const ulonglong2*)&wb[(k+1)*D_ + tc*8];
            const ulonglong2 wb1 = *(const ulonglong2*)&wb[(k+1)*D_ + tc*8 + 4];
#pragma unroll
            for (int u = 0; u < 8; u++) {
                const float2 xv = *(const float2*)&xb[(tr*8+u)*XPITCH + k];
                const u64 a0 = bc2(xv.x);
                const u64 a1 = bc2(xv.y);
                fma2(acc2[u][0], a0, wa0.x);
                fma2(acc2[u][1], a0, wa0.y);
                fma2(acc2[u][2], a0, wa1.x);
                fma2(acc2[u][3], a0, wa1.y);
                fma2(acc2[u][0], a1, wb0.x);
                fma2(acc2[u][1], a1, wb0.y);
                fma2(acc2[u][2], a1, wb1.x);
                fma2(acc2[u][3], a1, wb1.y);
            }
        }
    }

    float badd[8] = {0,0,0,0,0,0,0,0};
    if (m == 3) {
        float4 t0 = ((const float4*)bs)[tc*2];
        float4 t1 = ((const float4*)bs)[tc*2+1];
        badd[0]=t0.x; badd[1]=t0.y; badd[2]=t0.z; badd[3]=t0.w;
        badd[4]=t1.x; badd[5]=t1.y; badd[6]=t1.z; badd[7]=t1.w;
    }
#pragma unroll
    for (int u = 0; u < 8; u++) {
        float o[8];
#pragma unroll
        for (int p = 0; p < 4; p++) {
            const float2 t = unp2(acc2[u][p]);
            o[2*p] = t.x; o[2*p+1] = t.y;
        }
#pragma unroll
        for (int v = 0; v < 8; v++) {
            float val = o[v];
            if (m <= 1) val = (val > 0.f) ? (val + 1.f) : expf(val);   // elu + 1
            o[v] = val + badd[v];
        }
        float* dst = Op + ((size_t)(row0 + tr*8 + u))*D_ + tc*8;
        *(float4*)(dst)   = make_float4(o[0], o[1], o[2], o[3]);
        *(float4*)(dst+4) = make_float4(o[4], o[5], o[6], o[7]);
    }
}

// ---------------- k2: per-chunk outer-product sums + K sums (per half) ----------------
__global__ void k2_chunksum(int b_off) {
    const int c = blockIdx.x, b = blockIdx.y + b_off;
    const int tid = threadIdx.x;   // 256
    __shared__ __align__(16) float Ks[L_][D_];
    __shared__ __align__(16) float Vs[L_][D_];
    {
        const float4* kg = (const float4*)(g_K + ((size_t)b*T_ + c*L_)*D_);
        const float4* vg = (const float4*)(g_V + ((size_t)b*T_ + c*L_)*D_);
        for (int q = tid; q < L_*D_/4; q += 256) { ((float4*)Ks)[q] = kg[q]; ((float4*)Vs)[q] = vg[q]; }
    }
    __syncthreads();

    if (tid < D_) {
        float zs = 0.f;
#pragma unroll
        for (int t = 0; t < L_; t++) zs += Ks[t][tid];
        g_Zsum[((size_t)(b*C_ + c))*D_ + tid] = zs;
    }

    const int tr = tid >> 4, tc = tid & 15;
    const int i0 = tr*8, j0 = tc*8;
    float acc[8][8];
#pragma unroll
    for (int u = 0; u < 8; u++)
#pragma unroll
        for (int v = 0; v < 8; v++) acc[u][v] = 0.f;

    for (int t = 0; t < L_; t++) {
        float k8[8], v8[8];
        *(float4*)(k8)   = *(const float4*)&Ks[t][i0];
        *(float4*)(k8+4) = *(const float4*)&Ks[t][i0+4];
        *(float4*)(v8)   = *(const float4*)&Vs[t][j0];
        *(float4*)(v8+4) = *(const float4*)&Vs[t][j0+4];
#pragma unroll
        for (int u = 0; u < 8; u++)
#pragma unroll
            for (int v = 0; v < 8; v++) acc[u][v] += k8[u]*v8[v];
    }
    float* op = g_Soff + (((size_t)(b*C_ + c))*D_ + i0)*D_ + j0;
#pragma unroll
    for (int u = 0; u < 8; u++) {
        *(float4*)(op + (size_t)u*D_)     = make_float4(acc[u][0],acc[u][1],acc[u][2],acc[u][3]);
        *(float4*)(op + (size_t)u*D_ + 4) = make_float4(acc[u][4],acc[u][5],acc[u][6],acc[u][7]);
    }
}

// ---------------- k3: exclusive scan over c (per half) ----------------
__global__ void k3_scan(int b_off) {
    const int gid = blockIdx.x * blockDim.x + threadIdx.x;
    if (gid < BH_*D_*D_/4) {                // 16384
        const int b = (gid >> 12) + b_off;
        const int q = gid & 4095;
        float4* p = ((float4*)g_Soff) + (size_t)b*C_*4096 + q;
        float4 v[C_];
#pragma unroll
        for (int c = 0; c < C_; c++) v[c] = p[(size_t)c*4096];
        float rx=0.f, ry=0.f, rz=0.f, rw=0.f;
#pragma unroll
        for (int c = 0; c < C_; c++) {
            const float4 t = v[c];
            v[c] = make_float4(rx, ry, rz, rw);
            rx += t.x; ry += t.y; rz += t.z; rw += t.w;
        }
#pragma unroll
        for (int c = 0; c < C_; c++) p[(size_t)c*4096] = v[c];
    } else if (gid < BH_*D_*D_/4 + BH_*D_/4) {
        const int zid = gid - BH_*D_*D_/4;
        const int b = (zid >> 5) + b_off, q = zid & 31;
        float4* p = ((float4*)g_Zsum) + (size_t)b*C_*32 + q;
        float4 v[C_];
#pragma unroll
        for (int c = 0; c < C_; c++) v[c] = p[(size_t)c*32];
        float rx=0.f, ry=0.f, rz=0.f, rw=0.f;
#pragma unroll
        for (int c = 0; c < C_; c++) {
            const float4 t = v[c];
            v[c] = make_float4(rx, ry, rz, rw);
            rx += t.x; ry += t.y; rz += t.z; rw += t.w;
        }
#pragma unroll
        for (int c = 0; c < C_; c++) p[(size_t)c*32] = v[c];
    }
}

// ---------------- k4: j-split streaming scan + num/den (per half) ----------------
__global__ void __launch_bounds__(512, 2)
k4_scan(const float* __restrict__ S0, const float* __restrict__ Z0,
        float* __restrict__ outS, float* __restrict__ outZ, int b_off) {
    const int c = blockIdx.x, b = blockIdx.y + b_off, jh = blockIdx.z;
    const int tid = threadIdx.x;         // 512
    const int ig = tid >> 4;             // 0..31
    const int jg = tid & 15;             // 0..15
    const int i0 = ig << 2;
    const int j0 = jg << 2;
    const int jbase = jh * JH_;

    __shared__ __align__(16) float Ks[L_*D_];
    __shared__ __align__(16) float Qs[L_*D_];
    __shared__ __align__(16) float Vh[L_*JH_];
    __shared__ __align__(16) float A[L_*L_];
    __shared__ float zv[D_];
    __shared__ float sden[L_];

    const size_t base = ((size_t)b*T_ + c*L_)*D_;

    {
        ((float4*)Ks)[tid]       = ((const float4*)(g_K + base))[tid];
        ((float4*)Ks)[tid + 512] = ((const float4*)(g_K + base))[tid + 512];
        ((float4*)Qs)[tid]       = ((const float4*)(g_Q + base))[tid];
        ((float4*)Qs)[tid + 512] = ((const float4*)(g_Q + base))[tid + 512];
        const int t = tid >> 4;
        const int q = tid & 15;
        ((float4*)Vh)[tid] = *(const float4*)(g_V + base + (size_t)t*D_ + jbase + q*4);
    }

    float s[4][4];
    {
        const float* soff = g_Soff + ((size_t)(b*C_ + c)*D_ + i0)*D_ + jbase + j0;
        const float* s0g  = S0 + ((size_t)b*D_ + i0)*D_ + jbase + j0;
#pragma unroll
        for (int u = 0; u < 4; u++) {
            const float4 a = *(const float4*)(soff + (size_t)u*D_);
            const float4 z = *(const float4*)(s0g  + (size_t)u*D_);
            s[u][0] = a.x + z.x; s[u][1] = a.y + z.y;
            s[u][2] = a.z + z.z; s[u][3] = a.w + z.w;
        }
    }
    float zrun = 0.f;
    if (tid < D_) {
        zrun = Z0[b*D_ + tid] + g_Zsum[(size_t)(b*C_ + c)*D_ + tid];
        if (jh == 0) zv[tid] = zrun;
    }
    __syncthreads();

    // phase 1: streaming scan
    {
        float* op = outS + ((size_t)(b*T_ + c*L_))*D_*D_ + (size_t)i0*D_ + jbase + j0;
        float* zp = outZ + base;
        for (int tt = 0; tt < L_; tt++) {
            const float4 kv = *(const float4*)&Ks[tt*D_ + i0];
            const float4 vv = *(const float4*)&Vh[tt*JH_ + j0];
            const float kk[4] = {kv.x, kv.y, kv.z, kv.w};
#pragma unroll
            for (int u = 0; u < 4; u++) {
                s[u][0] += kk[u]*vv.x;
                s[u][1] += kk[u]*vv.y;
                s[u][2] += kk[u]*vv.z;
                s[u][3] += kk[u]*vv.w;
                __stcs((float4*)(op + (size_t)u*D_),
                       make_float4(s[u][0], s[u][1], s[u][2], s[u][3]));
            }
            if (jh == 0 && tid < D_) { zrun += Ks[tt*D_ + tid]; zp[tid] = zrun; }
            op += (size_t)D_*D_;
            zp += D_;
        }
    }

    // phase 2a: masked A = QK^T; den on jh==0
    if (tid < 256) {
        const int ti = tid >> 3;
        const int g  = tid & 7;
        float a4[4] = {0.f, 0.f, 0.f, 0.f};
        for (int k = 0; k < D_; k += 4) {
            const float4 qv = *(const float4*)&Qs[ti*D_ + k];
#pragma unroll
            for (int j = 0; j < 4; j++) {
                const float4 kv = *(const float4*)&Ks[(g*4+j)*D_ + k];
                a4[j] += qv.x*kv.x + qv.y*kv.y + qv.z*kv.z + qv.w*kv.w;
            }
        }
        float rsum = 0.f;
#pragma unroll
        for (int j = 0; j < 4; j++) {
            const int tj = g*4 + j;
            const float mval = (tj <= ti) ? a4[j] : 0.f;
            A[ti*L_ + tj] = mval;
            rsum += mval;
        }
        if (jh == 0) {
            float zp = 0.f;
#pragma unroll
            for (int k = 0; k < 16; k += 4) {
                const float4 qv = *(const float4*)&Qs[ti*D_ + g*16 + k];
                const float4 zz = *(const float4*)&zv[g*16 + k];
                zp += qv.x*zz.x + qv.y*zz.y + qv.z*zz.z + qv.w*zz.w;
            }
            float tot = rsum + zp;
#pragma unroll
            for (int off = 4; off; off >>= 1) tot += __shfl_down_sync(0xffffffffu, tot, off);
            if (g == 0) sden[ti] = tot;
        }
    }
    __syncthreads();

    // phase 2b: numerator half
    const int row = tid >> 4;
    const int cg  = (tid & 15) * 4;
    float nacc[4] = {0.f, 0.f, 0.f, 0.f};
    for (int tj = 0; tj <= row; tj++) {
        const float a = A[row*L_ + tj];
        const float4 vv = *(const float4*)&Vh[tj*JH_ + cg];
        nacc[0] += a*vv.x; nacc[1] += a*vv.y;
        nacc[2] += a*vv.z; nacc[3] += a*vv.w;
    }
    {
        const float* s0p = S0 + (size_t)b*D_*D_ + jbase;
        const float* sop = g_Soff + (size_t)(b*C_ + c)*D_*D_ + jbase;
        for (int kb = 0; kb < D_; kb += 32) {
            __syncthreads();
            {
                const int r = tid >> 4;
                const int q = tid & 15;
                const float4 x0 = __ldg((const float4*)(s0p + (size_t)(kb + r)*D_) + q);
                const float4 x1 = __ldg((const float4*)(sop + (size_t)(kb + r)*D_) + q);
                ((float4*)Vh)[tid] = make_float4(x0.x+x1.x, x0.y+x1.y, x0.z+x1.z, x0.w+x1.w);
            }
            __syncthreads();
#pragma unroll 8
            for (int k = 0; k < 32; k++) {
                const float qq = Qs[row*D_ + kb + k];
                const float4 sv = *(const float4*)&Vh[k*JH_ + cg];
                nacc[0] += qq*sv.x; nacc[1] += qq*sv.y;
                nacc[2] += qq*sv.z; nacc[3] += qq*sv.w;
            }
        }
    }
    *(float4*)(g_num + base + (size_t)row*D_ + jbase + cg) =
        make_float4(nacc[0], nacc[1], nacc[2], nacc[3]);
    if (jh == 0 && tid < L_)
        g_den[(size_t)b*T_ + c*L_ + tid] = sden[tid];
}

// ---------------- k5: FFN + residual (per half) ----------------
__global__ void k5_ffn(const float* __restrict__ W1, const float* __restrict__ b1_,
                       const float* __restrict__ W2, const float* __restrict__ b2_,
                       float* __restrict__ outO, int row_off) {
    __shared__ __align__(16) float aBuf[32*D_];
    __shared__ __align__(16) float wBuf[32*D_];
    const int tid  = threadIdx.x;  // 256
    const int w    = tid >> 5, lane = tid & 31;
    const int row0 = row_off + blockIdx.x * 32;

#pragma unroll
    for (int rr = 0; rr < 4; rr++) {
        const int r = w*4 + rr;
        const size_t row = (size_t)row0 + r;
        const float rden = 1.0f / (g_den[row] + 1e-5f);
#pragma unroll
        for (int k = 0; k < 4; k++) {
            const int f = lane + 32*k;
            aBuf[r*D_ + f] = g_num[row*D_ + f] * rden;
        }
    }
    const int rowg = w, colg = lane;
    float acc[4][4];

#pragma unroll
    for (int u = 0; u < 4; u++)
#pragma unroll
        for (int v = 0; v < 4; v++) acc[u][v] = 0.f;
    for (int kc = 0; kc < D_; kc += 32) {
        __syncthreads();
        for (int q = tid; q < 32*D_/4; q += 256)
            ((float4*)wBuf)[q] = ((const float4*)(W1 + (size_t)kc*D_))[q];
        __syncthreads();
#pragma unroll
        for (int k = 0; k < 32; k++) {
            const float4 wv = ((const float4*)(wBuf + k*D_))[colg];
#pragma unroll
            for (int u = 0; u < 4; u++) {
                const float a = aBuf[(rowg*4+u)*D_ + kc + k];
                acc[u][0] += a*wv.x; acc[u][1] += a*wv.y;
                acc[u][2] += a*wv.z; acc[u][3] += a*wv.w;
            }
        }
    }
    __syncthreads();
    {
        const float4 b1v = ((const float4*)b1_)[colg];
#pragma unroll
        for (int u = 0; u < 4; u++) {
            float4 h;
            h.x = fmaxf(acc[u][0] + b1v.x, 0.f);
            h.y = fmaxf(acc[u][1] + b1v.y, 0.f);
            h.z = fmaxf(acc[u][2] + b1v.z, 0.f);
            h.w = fmaxf(acc[u][3] + b1v.w, 0.f);
            *(float4*)&aBuf[(rowg*4+u)*D_ + colg*4] = h;
        }
    }
#pragma unroll
    for (int u = 0; u < 4; u++)
#pragma unroll
        for (int v = 0; v < 4; v++) acc[u][v] = 0.f;
    for (int kc = 0; kc < D_; kc += 32) {
        __syncthreads();
        for (int q = tid; q < 32*D_/4; q += 256)
            ((float4*)wBuf)[q] = ((const float4*)(W2 + (size_t)kc*D_))[q];
        __syncthreads();
#pragma unroll
        for (int k = 0; k < 32; k++) {
            const float4 wv = ((const float4*)(wBuf + k*D_))[colg];
#pragma unroll
            for (int u = 0; u < 4; u++) {
                const float a = aBuf[(rowg*4+u)*D_ + kc + k];
                acc[u][0] += a*wv.x; acc[u][1] += a*wv.y;
                acc[u][2] += a*wv.z; acc[u][3] += a*wv.w;
            }
        }
    }
    {
        const float4 b2v = ((const float4*)b2_)[colg];
#pragma unroll
        for (int u = 0; u < 4; u++) {
            const size_t row = (size_t)row0 + rowg*4 + u;
            const float4 rv = *(const float4*)(g_R + row*D_ + colg*4);
            float4 o;
            o.x = fmaxf(acc[u][0] + b2v.x, 0.f) + rv.x;
            o.y = fmaxf(acc[u][1] + b2v.y, 0.f) + rv.y;
            o.z = fmaxf(acc[u][2] + b2v.z, 0.f) + rv.z;
            o.w = fmaxf(acc[u][3] + b2v.w, 0.f) + rv.w;
            *(float4*)(outO + row*D_ + colg*4) = o;
        }
    }
}

// ---------------- launch: two independent batch-half chains ----------------
static cudaStream_t s2 = nullptr;
static cudaEvent_t eRoot = nullptr, eB = nullptr;

extern "C" void kernel_launch(void* const* d_in, const int* in_sizes, int n_in,
                              void* d_out, int out_size) {
    const float* x     = (const float*)d_in[0];
    const float* S0    = (const float*)d_in[1];
    const float* Z0    = (const float*)d_in[2];
    const float* gamma = (const float*)d_in[3];
    const float* beta  = (const float*)d_in[4];
    const float* Wk    = (const float*)d_in[5];
    const float* Wq    = (const float*)d_in[6];
    const float* Wv    = (const float*)d_in[7];
    const float* W1    = (const float*)d_in[8];
    const float* b1    = (const float*)d_in[9];
    const float* W2    = (const float*)d_in[10];
    const float* b2    = (const float*)d_in[11];
    const float* Ws    = (const float*)d_in[12];
    const float* bs    = (const float*)d_in[13];

    float* outO = (float*)d_out;
    float* outS = outO + (size_t)B_*T_*D_;
    float* outZ = outS + (size_t)B_*T_*D_*D_;

    if (!s2) {
        cudaStreamCreateWithFlags(&s2, cudaStreamNonBlocking);
        cudaEventCreateWithFlags(&eRoot, cudaEventDisableTiming);
        cudaEventCreateWithFlags(&eB, cudaEventDisableTiming);
    }

    const int rowsH  = BH_*T_;             // 2048 rows per half
    const int k3blk  = (BH_*D_*D_/4 + BH_*D_/4 + 255)/256;

    cudaEventRecord(eRoot, 0);
    cudaStreamWaitEvent(s2, eRoot, 0);

    // chain A (b 0..3) on stream 0
    k0_ln<<<rowsH/32, 256>>>(x, gamma, beta, 0);
    k1_proj<<<dim3(rowsH/128, 4), 256>>>(Wk, Wq, Wv, Ws, bs, 0);
    k2_chunksum<<<dim3(C_, BH_), 256>>>(0);
    k3_scan<<<k3blk, 256>>>(0);
    k4_scan<<<dim3(C_, BH_, 2), 512>>>(S0, Z0, outS, outZ, 0);
    k5_ffn<<<rowsH/32, 256>>>(W1, b1, W2, b2, outO, 0);

    // chain B (b 4..7) on stream s2
    k0_ln<<<rowsH/32, 256, 0, s2>>>(x, gamma, beta, rowsH);
    k1_proj<<<dim3(rowsH/128, 4), 256, 0, s2>>>(Wk, Wq, Wv, Ws, bs, rowsH);
    k2_chunksum<<<dim3(C_, BH_), 256, 0, s2>>>(BH_);
    k3_scan<<<k3blk, 256, 0, s2>>>(BH_);
    k4_scan<<<dim3(C_, BH_, 2), 512, 0, s2>>>(S0, Z0, outS, outZ, BH_);
    k5_ffn<<<rowsH/32, 256, 0, s2>>>(W1, b1, W2, b2, outO, rowsH);
    cudaEventRecord(eB, s2);

    cudaStreamWaitEvent(0, eB, 0);
}